// round 10
// baseline (speedup 1.0000x reference)
#include <cuda_runtime.h>
#include <cuda_bf16.h>
#include <cstdint>

#define THREADS 256
#define NCHUNKS_TOT 273          // L0:17 (folded 528+16 pad)  L1:128  L2:128

// A in mma-fragment-linear layout:
// uint4 index = ((chunk*8 + mtrole)*8 + q)*32 + lane,  q = ks*4 + mh*2 + term
__device__ __align__(16) uint4 g_Wfrag[(size_t)NCHUNKS_TOT * 8 * 8 * 32];
// layer-0 slot table: (m<<8)|n per folded slot; pad slots -> (32,32)
__device__ __align__(4) uint16_t g_tab[544];

// ---- SMEM layout (bytes), per 256-thread CTA (1 batch) ----
#define BBUF_OFF 0                 // 2 groups x 2 bufs x 8192 = 32768
#define XS_OFF   32768             // 33 x 65 x 4 = 8580 -> 8608
#define HS_OFF   41376             // 128 x 65 x 4 = 33280
#define TAB_OFF  74656             // 544 x 2 = 1088
#define RED_OFF  75744             // 8 floats
#define SMEM_BYTES (RED_OFF + 64)

__device__ __forceinline__ uint32_t smem_u32(const void* p) {
    uint32_t a;
    asm("{ .reg .u64 t; cvta.to.shared.u64 t, %1; cvt.u32.u64 %0, t; }" : "=r"(a) : "l"(p));
    return a;
}
__device__ __forceinline__ uint32_t sw128(uint32_t o) { return o ^ ((o >> 3) & 0x70); }
__device__ __forceinline__ uint32_t pkbf(float a, float b) {
    __nv_bfloat16 ha = __float2bfloat16(a), hb = __float2bfloat16(b);
    return (uint32_t)__bfloat16_as_ushort(ha) | ((uint32_t)__bfloat16_as_ushort(hb) << 16);
}
__device__ __forceinline__ void ldsm4(uint32_t* r, uint32_t addr) {
    asm volatile("ldmatrix.sync.aligned.m8n8.x4.shared.b16 {%0,%1,%2,%3}, [%4];"
                 : "=r"(r[0]), "=r"(r[1]), "=r"(r[2]), "=r"(r[3]) : "r"(addr));
}
__device__ __forceinline__ void mma16816_u4(float* c, const uint4& a, const uint32_t* b) {
    asm volatile("mma.sync.aligned.m16n8k16.row.col.f32.bf16.bf16.f32 "
                 "{%0,%1,%2,%3}, {%4,%5,%6,%7}, {%8,%9}, {%0,%1,%2,%3};"
                 : "+f"(c[0]), "+f"(c[1]), "+f"(c[2]), "+f"(c[3])
                 : "r"(a.x), "r"(a.y), "r"(a.z), "r"(a.w), "r"(b[0]), "r"(b[1]));
}
__device__ __forceinline__ uint32_t pk_term(float v0, float v1, int term) {
    if (term == 0) return pkbf(v0, v1);
    const __nv_bfloat16 h0 = __float2bfloat16(v0), h1 = __float2bfloat16(v1);
    return pkbf(v0 - __bfloat162float(h0), v1 - __bfloat162float(h1));
}
__device__ __forceinline__ void unrank(int t, int& m, int& n) {
    int mm = 0, base = 0;
    while (base + (32 - mm) <= t) { base += 32 - mm; ++mm; }
    m = mm; n = mm + (t - base);
}

// ---------------- pre-pass: write A fragments + slot table ----------------
__global__ __launch_bounds__(512) void prep_kernel(
    const float* __restrict__ W0, const float* __restrict__ W1, const float* __restrict__ W2)
{
    const int g = blockIdx.x;

    if (g == 0) {
        for (int t = threadIdx.x; t < 544; t += 512) {
            int m = 32, n = 32;
            if (t < 528) unrank(t, m, n);
            g_tab[t] = (uint16_t)((m << 8) | n);
        }
    }

    auto wv = [&](int slot, int row) -> float {
        if (g < 17) {
            const int t = g * 32 + slot;
            if (t >= 528) return 0.0f;
            int m, n; unrank(t, m, n);
            float v = W0[(size_t)(m * 32 + n) * 256 + row];
            if (m != n) v += W0[(size_t)(n * 32 + m) * 256 + row];
            return v;
        } else if (g < 145) {
            return W1[(size_t)((g - 17) * 32 + slot) * 256 + row];
        } else {
            return W2[(size_t)((g - 145) * 32 + slot) * 256 + row];
        }
    };

    #pragma unroll
    for (int i = 0; i < 4; ++i) {
        const int idx  = threadIdx.x + i * 512;   // 0..2047
        const int lane = idx & 31;
        const int q    = (idx >> 5) & 7;
        const int mt   = idx >> 8;                // warp role 0..7
        const int ks   = q >> 2, mh = (q >> 1) & 1, term = q & 1;
        const int r    = mt * 32 + mh * 16 + (lane >> 2);
        const int k0   = ks * 16 + (lane & 3) * 2;

        uint4 o;
        o.x = pk_term(wv(k0,     r),     wv(k0 + 1, r),     term);
        o.y = pk_term(wv(k0,     r + 8), wv(k0 + 1, r + 8), term);
        o.z = pk_term(wv(k0 + 8, r),     wv(k0 + 9, r),     term);
        o.w = pk_term(wv(k0 + 8, r + 8), wv(k0 + 9, r + 8), term);
        g_Wfrag[((size_t)g * 8 + mt) * 256 + q * 32 + lane] = o;
    }
}

// ---------------- main kernel: 1 batch/CTA, 2 CTAs/SM, split 128-thread groups ----------------
__global__ __launch_bounds__(THREADS, 2) void cin_mma_kernel(
    const float* __restrict__ x,
    const float* __restrict__ b0, const float* __restrict__ b1, const float* __restrict__ b2,
    const float* __restrict__ fcW, const float* __restrict__ fcb,
    float* __restrict__ out)
{
    extern __shared__ unsigned char smem[];
    const uint32_t sbase = smem_u32(smem);
    float* xs  = (float*)(smem + XS_OFF);
    float* hs  = (float*)(smem + HS_OFF);
    uint16_t* tab = (uint16_t*)(smem + TAB_OFF);
    float* red = (float*)(smem + RED_OFF);

    const int tid = threadIdx.x, wid = tid >> 5, lane = tid & 31;
    const int B = blockIdx.x;
    const int mt = wid;
    const int group = tid >> 7;               // 0: warps 0-3, 1: warps 4-7
    const int gtid  = tid & 127;

    // B ldmatrix lane addressing
    const int brl  = ((lane >> 4) << 3) + (lane & 7);
    const int bk16 = ((lane >> 3) & 1) * 16;

    // z-build mapping: 128 threads per group build 64 rows x 32 k (16 elems each)
    const int brow = gtid >> 1;               // 0..63 (d)
    const int seg  = (gtid & 1) * 16;         // k offset 0 or 16
    const float* biasl[3] = {b0, b1, b2};

    // stage x into padded xs (stride 65), zero row 32, load slot table
    #pragma unroll
    for (int i = 0; i < 2; ++i) {
        const int idx = tid + i * 256;
        const float4 v = ((const float4*)(x + (size_t)B * 2048))[idx];
        const int f = idx * 4;
        float* dp = xs + (f >> 6) * 65 + (f & 63);
        dp[0] = v.x; dp[1] = v.y; dp[2] = v.z; dp[3] = v.w;
    }
    if (tid < 65) xs[32 * 65 + tid] = 0.0f;
    for (int i = tid; i < 272; i += THREADS)
        ((uint32_t*)tab)[i] = ((const uint32_t*)g_tab)[i];
    __syncthreads();

    float fc_acc = 0.0f;
    const int r0 = lane >> 2;

    auto gbar = [&]() {
        asm volatile("bar.sync %0, %1;" :: "r"(1 + group), "r"(128) : "memory");
    };

    for (int layer = 0; layer < 3; ++layer) {
        const int nch = (layer == 0) ? 17 : 128;
        const int gW  = (layer == 0) ? 0 : ((layer == 1) ? 17 : 145);

        float acc[2][8][4];
        #pragma unroll
        for (int a = 0; a < 2; ++a)
            #pragma unroll
            for (int j = 0; j < 8; ++j)
                #pragma unroll
                for (int e = 0; e < 4; ++e) acc[a][j][e] = 0.0f;

        auto buildB = [&](int cc, int buf) {
            uint32_t hpk[8], lpk[8];
            if (layer == 0) {
                const int kb = cc * 32 + seg;
                #pragma unroll
                for (int j = 0; j < 8; ++j) {
                    const uint32_t t0 = tab[kb + 2 * j], t1 = tab[kb + 2 * j + 1];
                    const float p0 = xs[(t0 >> 8) * 65 + brow] * xs[(t0 & 255) * 65 + brow];
                    const float p1 = xs[(t1 >> 8) * 65 + brow] * xs[(t1 & 255) * 65 + brow];
                    const __nv_bfloat16 h0 = __float2bfloat16(p0), h1 = __float2bfloat16(p1);
                    hpk[j] = (uint32_t)__bfloat16_as_ushort(h0) |
                             ((uint32_t)__bfloat16_as_ushort(h1) << 16);
                    lpk[j] = pkbf(p0 - __bfloat162float(h0), p1 - __bfloat162float(h1));
                }
            } else {
                const int m = cc >> 2, nb = (cc & 3) * 32 + seg;
                const float xv = xs[m * 65 + brow];
                #pragma unroll
                for (int j = 0; j < 8; ++j) {
                    const float p0 = xv * hs[(nb + 2 * j) * 65 + brow];
                    const float p1 = xv * hs[(nb + 2 * j + 1) * 65 + brow];
                    const __nv_bfloat16 h0 = __float2bfloat16(p0), h1 = __float2bfloat16(p1);
                    hpk[j] = (uint32_t)__bfloat16_as_ushort(h0) |
                             ((uint32_t)__bfloat16_as_ushort(h1) << 16);
                    lpk[j] = pkbf(p0 - __bfloat162float(h0), p1 - __bfloat162float(h1));
                }
            }
            unsigned char* bbs = smem + BBUF_OFF + group * 16384 + buf * 8192;
            const uint32_t offh = brow * 128 + seg * 2;
            *(uint4*)(bbs + sw128(offh))      = make_uint4(hpk[0], hpk[1], hpk[2], hpk[3]);
            *(uint4*)(bbs + sw128(offh + 16)) = make_uint4(hpk[4], hpk[5], hpk[6], hpk[7]);
            *(uint4*)(bbs + sw128(offh + 64)) = make_uint4(lpk[0], lpk[1], lpk[2], lpk[3]);
            *(uint4*)(bbs + sw128(offh + 80)) = make_uint4(lpk[4], lpk[5], lpk[6], lpk[7]);
        };

        auto loadA = [&](uint4* Aq, int chunk, int ks) {
            const uint4* __restrict__ P =
                g_Wfrag + ((size_t)chunk * 8 + mt) * 256 + ks * 128 + lane;
            #pragma unroll
            for (int q = 0; q < 4; ++q) Aq[q] = P[q * 32];
        };

        auto computeKs = [&](const uint4* Aq, uint32_t bbse, int ks) {
            #pragma unroll
            for (int jj = 0; jj < 4; ++jj) {
                const uint32_t boff = (uint32_t)(jj * 16 + brl) * 128 + 32 * ks + bk16;
                uint32_t Bh[4], Bl[4];
                ldsm4(Bh, bbse + sw128(boff));
                ldsm4(Bl, bbse + sw128(boff + 64));
                #pragma unroll
                for (int mh = 0; mh < 2; ++mh) {
                    #pragma unroll
                    for (int jq = 0; jq < 2; ++jq) {
                        float* cc2 = acc[mh][2 * jj + jq];
                        mma16816_u4(cc2, Aq[mh * 2 + 0], Bh + 2 * jq);  // hi*hi
                        mma16816_u4(cc2, Aq[mh * 2 + 0], Bl + 2 * jq);  // hi*lo
                        mma16816_u4(cc2, Aq[mh * 2 + 1], Bh + 2 * jq);  // lo*hi
                    }
                }
            }
        };

        uint4 Acur[4], Anext[4];
        buildB(0, 0);
        loadA(Acur, gW, 0);
        gbar();

        for (int c = 0; c < nch; ++c) {
            const int buf = c & 1;
            const uint32_t bbse = sbase + BBUF_OFF + group * 16384 + buf * 8192;
            const int cn = (c + 1 < nch) ? c + 1 : c;

            loadA(Anext, gW + c, 1);
            if (c + 1 < nch) buildB(c + 1, buf ^ 1);
            computeKs(Acur, bbse, 0);
            loadA(Acur, gW + cn, 0);
            computeKs(Anext, bbse, 1);
            gbar();
        }
        __syncthreads();   // both groups done reading hs before it is overwritten

        // ---- epilogue ----
        const float* bl = biasl[layer];
        const int fcbase = (layer == 2) ? 256 : layer * 128;
        const bool do_fc = (layer == 2) || (mt < 4);
        float bias4[4], fw4[4];
        #pragma unroll
        for (int rr = 0; rr < 4; ++rr) {
            const int row = mt * 32 + rr * 8 + r0;
            bias4[rr] = bl[row];
            fw4[rr] = do_fc ? fcW[fcbase + row] : 0.0f;
        }
        #pragma unroll
        for (int mh = 0; mh < 2; ++mh) {
            #pragma unroll
            for (int j = 0; j < 8; ++j) {
                #pragma unroll
                for (int e = 0; e < 4; ++e) {
                    const int rr = mh * 2 + (e >> 1);
                    const float v = fmaxf(acc[mh][j][e] + bias4[rr], 0.0f);
                    if (do_fc) {
                        fc_acc += fw4[rr] * v;
                    } else {
                        const int row = mt * 32 + mh * 16 + (e >> 1) * 8 + r0;
                        const int d   = 8 * j + 2 * (lane & 3) + (e & 1);
                        hs[(row - 128) * 65 + d] = v;
                    }
                }
            }
        }
        __syncthreads();
    }

    // final reduction (single batch)
    #pragma unroll
    for (int off = 16; off > 0; off >>= 1)
        fc_acc += __shfl_xor_sync(0xffffffffu, fc_acc, off);
    if (lane == 0) red[wid] = fc_acc;
    __syncthreads();
    if (tid == 0) {
        float s = 0.0f;
        #pragma unroll
        for (int w = 0; w < 8; ++w) s += red[w];
        out[B] = s + fcb[0];
    }
}

extern "C" void kernel_launch(void* const* d_in, const int* in_sizes, int n_in,
                              void* d_out, int out_size) {
    const float* x   = (const float*)d_in[0];
    const float* W0  = (const float*)d_in[1];
    const float* b0  = (const float*)d_in[2];
    const float* W1  = (const float*)d_in[3];
    const float* b1  = (const float*)d_in[4];
    const float* W2  = (const float*)d_in[5];
    const float* b2  = (const float*)d_in[6];
    const float* fcW = (const float*)d_in[7];
    const float* fcb = (const float*)d_in[8];
    float* out = (float*)d_out;

    cudaFuncSetAttribute(cin_mma_kernel, cudaFuncAttributeMaxDynamicSharedMemorySize, SMEM_BYTES);
    prep_kernel<<<NCHUNKS_TOT, 512>>>(W0, W1, W2);
    cin_mma_kernel<<<1024, THREADS, SMEM_BYTES>>>(x, b0, b1, b2, fcW, fcb, out);
}

// round 11
// speedup vs baseline: 1.1363x; 1.1363x over previous
#include <cuda_runtime.h>
#include <cuda_bf16.h>
#include <cstdint>

#define THREADS 256
#define NCHUNKS_TOT 273          // L0:17 (folded 528+16 pad)  L1:128  L2:128

// A in mma-fragment-linear layout:
// uint4 index = ((chunk*8 + mtrole)*8 + q)*32 + lane,  q = ks*4 + mh*2 + term
__device__ __align__(16) uint4 g_Wfrag[(size_t)NCHUNKS_TOT * 8 * 8 * 32];
// layer-0 slot table: (m<<8)|n per folded slot; pad slots -> (32,32)
__device__ __align__(4) uint16_t g_tab[544];

// ---- SMEM layout (bytes), per 256-thread CTA (1 batch) ----
#define BBUF_OFF 0                 // 2 x 8192
#define XS_OFF   16384             // 33 x 65 x 4 = 8580 -> 8608
#define HS_OFF   24992             // 128 x 65 x 4 = 33280
#define TAB_OFF  58272             // 544 x 2 = 1088
#define RED_OFF  59360             // 8 floats
#define SMEM_BYTES (RED_OFF + 64)

__device__ __forceinline__ uint32_t smem_u32(const void* p) {
    uint32_t a;
    asm("{ .reg .u64 t; cvta.to.shared.u64 t, %1; cvt.u32.u64 %0, t; }" : "=r"(a) : "l"(p));
    return a;
}
__device__ __forceinline__ uint32_t sw128(uint32_t o) { return o ^ ((o >> 3) & 0x70); }
__device__ __forceinline__ uint32_t pkbf(float a, float b) {
    __nv_bfloat16 ha = __float2bfloat16(a), hb = __float2bfloat16(b);
    return (uint32_t)__bfloat16_as_ushort(ha) | ((uint32_t)__bfloat16_as_ushort(hb) << 16);
}
__device__ __forceinline__ void ldsm4(uint32_t* r, uint32_t addr) {
    asm volatile("ldmatrix.sync.aligned.m8n8.x4.shared.b16 {%0,%1,%2,%3}, [%4];"
                 : "=r"(r[0]), "=r"(r[1]), "=r"(r[2]), "=r"(r[3]) : "r"(addr));
}
__device__ __forceinline__ void mma16816_u4(float* c, const uint4& a, const uint32_t* b) {
    asm volatile("mma.sync.aligned.m16n8k16.row.col.f32.bf16.bf16.f32 "
                 "{%0,%1,%2,%3}, {%4,%5,%6,%7}, {%8,%9}, {%0,%1,%2,%3};"
                 : "+f"(c[0]), "+f"(c[1]), "+f"(c[2]), "+f"(c[3])
                 : "r"(a.x), "r"(a.y), "r"(a.z), "r"(a.w), "r"(b[0]), "r"(b[1]));
}
__device__ __forceinline__ uint32_t pk_term(float v0, float v1, int term) {
    if (term == 0) return pkbf(v0, v1);
    const __nv_bfloat16 h0 = __float2bfloat16(v0), h1 = __float2bfloat16(v1);
    return pkbf(v0 - __bfloat162float(h0), v1 - __bfloat162float(h1));
}
__device__ __forceinline__ void unrank(int t, int& m, int& n) {
    int mm = 0, base = 0;
    while (base + (32 - mm) <= t) { base += 32 - mm; ++mm; }
    m = mm; n = mm + (t - base);
}

// ---------------- pre-pass: write A fragments + slot table ----------------
__global__ __launch_bounds__(512) void prep_kernel(
    const float* __restrict__ W0, const float* __restrict__ W1, const float* __restrict__ W2)
{
    const int g = blockIdx.x;

    if (g == 0) {
        for (int t = threadIdx.x; t < 544; t += 512) {
            int m = 32, n = 32;
            if (t < 528) unrank(t, m, n);
            g_tab[t] = (uint16_t)((m << 8) | n);
        }
    }

    auto wv = [&](int slot, int row) -> float {
        if (g < 17) {
            const int t = g * 32 + slot;
            if (t >= 528) return 0.0f;
            int m, n; unrank(t, m, n);
            float v = W0[(size_t)(m * 32 + n) * 256 + row];
            if (m != n) v += W0[(size_t)(n * 32 + m) * 256 + row];
            return v;
        } else if (g < 145) {
            return W1[(size_t)((g - 17) * 32 + slot) * 256 + row];
        } else {
            return W2[(size_t)((g - 145) * 32 + slot) * 256 + row];
        }
    };

    #pragma unroll
    for (int i = 0; i < 4; ++i) {
        const int idx  = threadIdx.x + i * 512;   // 0..2047
        const int lane = idx & 31;
        const int q    = (idx >> 5) & 7;
        const int mt   = idx >> 8;                // warp role 0..7
        const int ks   = q >> 2, mh = (q >> 1) & 1, term = q & 1;
        const int r    = mt * 32 + mh * 16 + (lane >> 2);
        const int k0   = ks * 16 + (lane & 3) * 2;

        uint4 o;
        o.x = pk_term(wv(k0,     r),     wv(k0 + 1, r),     term);
        o.y = pk_term(wv(k0,     r + 8), wv(k0 + 1, r + 8), term);
        o.z = pk_term(wv(k0 + 8, r),     wv(k0 + 9, r),     term);
        o.w = pk_term(wv(k0 + 8, r + 8), wv(k0 + 9, r + 8), term);
        g_Wfrag[((size_t)g * 8 + mt) * 256 + q * 32 + lane] = o;
    }
}

// ---------------- main kernel: 1 batch/CTA, 2 CTAs/SM, shared B, folded L0 ----------------
__global__ __launch_bounds__(THREADS, 2) void cin_mma_kernel(
    const float* __restrict__ x,
    const float* __restrict__ b0, const float* __restrict__ b1, const float* __restrict__ b2,
    const float* __restrict__ fcW, const float* __restrict__ fcb,
    float* __restrict__ out)
{
    extern __shared__ unsigned char smem[];
    const uint32_t sbase = smem_u32(smem);
    float* xs  = (float*)(smem + XS_OFF);
    float* hs  = (float*)(smem + HS_OFF);
    uint16_t* tab = (uint16_t*)(smem + TAB_OFF);
    float* red = (float*)(smem + RED_OFF);

    const int tid = threadIdx.x, wid = tid >> 5, lane = tid & 31;
    const int B = blockIdx.x;
    const int mt = wid;

    // B ldmatrix lane addressing
    const int brl  = ((lane >> 4) << 3) + (lane & 7);
    const int bk16 = ((lane >> 3) & 1) * 16;

    // z-build mapping (shared single build): row d = tid>>2, 8 k's per thread
    const int brow = tid >> 2;
    const int seg  = (tid & 3) * 8;
    const float* biasl[3] = {b0, b1, b2};

    // stage x into padded xs (stride 65); zero pad row 32; load slot table
    #pragma unroll
    for (int i = 0; i < 2; ++i) {
        const int idx = tid + i * 256;
        const float4 v = ((const float4*)(x + (size_t)B * 2048))[idx];
        const int f = idx * 4;
        float* dp = xs + (f >> 6) * 65 + (f & 63);
        dp[0] = v.x; dp[1] = v.y; dp[2] = v.z; dp[3] = v.w;
    }
    if (tid < 65) xs[32 * 65 + tid] = 0.0f;
    for (int i = tid; i < 272; i += THREADS)
        ((uint32_t*)tab)[i] = ((const uint32_t*)g_tab)[i];
    __syncthreads();

    float fc_acc = 0.0f;
    const int r0 = lane >> 2;

    for (int layer = 0; layer < 3; ++layer) {
        const int nch = (layer == 0) ? 17 : 128;
        const int gW  = (layer == 0) ? 0 : ((layer == 1) ? 17 : 145);

        float acc[2][8][4];
        #pragma unroll
        for (int a = 0; a < 2; ++a)
            #pragma unroll
            for (int j = 0; j < 8; ++j)
                #pragma unroll
                for (int e = 0; e < 4; ++e) acc[a][j][e] = 0.0f;

        auto buildB = [&](int cc, int buf) {
            uint32_t hpk[4], lpk[4];
            if (layer == 0) {
                const int kb = cc * 32 + seg;
                #pragma unroll
                for (int q = 0; q < 4; ++q) {
                    const uint32_t t0 = tab[kb + 2 * q], t1 = tab[kb + 2 * q + 1];
                    const float p0 = xs[(t0 >> 8) * 65 + brow] * xs[(t0 & 255) * 65 + brow];
                    const float p1 = xs[(t1 >> 8) * 65 + brow] * xs[(t1 & 255) * 65 + brow];
                    const __nv_bfloat16 h0 = __float2bfloat16(p0), h1 = __float2bfloat16(p1);
                    hpk[q] = (uint32_t)__bfloat16_as_ushort(h0) |
                             ((uint32_t)__bfloat16_as_ushort(h1) << 16);
                    lpk[q] = pkbf(p0 - __bfloat162float(h0), p1 - __bfloat162float(h1));
                }
            } else {
                const int m = cc >> 2, nb = (cc & 3) * 32 + seg;
                const float xv = xs[m * 65 + brow];
                #pragma unroll
                for (int q = 0; q < 4; ++q) {
                    const float p0 = xv * hs[(nb + 2 * q) * 65 + brow];
                    const float p1 = xv * hs[(nb + 2 * q + 1) * 65 + brow];
                    const __nv_bfloat16 h0 = __float2bfloat16(p0), h1 = __float2bfloat16(p1);
                    hpk[q] = (uint32_t)__bfloat16_as_ushort(h0) |
                             ((uint32_t)__bfloat16_as_ushort(h1) << 16);
                    lpk[q] = pkbf(p0 - __bfloat162float(h0), p1 - __bfloat162float(h1));
                }
            }
            unsigned char* bbs = smem + BBUF_OFF + buf * 8192;
            const uint32_t offh = brow * 128 + seg * 2;
            *(uint4*)(bbs + sw128(offh))      = make_uint4(hpk[0], hpk[1], hpk[2], hpk[3]);
            *(uint4*)(bbs + sw128(offh + 64)) = make_uint4(lpk[0], lpk[1], lpk[2], lpk[3]);
        };

        auto loadA = [&](uint4* Aq, int chunk, int ks) {
            const uint4* __restrict__ P =
                g_Wfrag + ((size_t)chunk * 8 + mt) * 256 + ks * 128 + lane;
            #pragma unroll
            for (int q = 0; q < 4; ++q) Aq[q] = P[q * 32];
        };

        auto computeKs = [&](const uint4* Aq, uint32_t bbse, int ks) {
            #pragma unroll
            for (int jj = 0; jj < 4; ++jj) {
                const uint32_t boff = (uint32_t)(jj * 16 + brl) * 128 + 32 * ks + bk16;
                uint32_t Bh[4], Bl[4];
                ldsm4(Bh, bbse + sw128(boff));
                ldsm4(Bl, bbse + sw128(boff + 64));
                #pragma unroll
                for (int mh = 0; mh < 2; ++mh) {
                    #pragma unroll
                    for (int jq = 0; jq < 2; ++jq) {
                        float* cc2 = acc[mh][2 * jj + jq];
                        mma16816_u4(cc2, Aq[mh * 2 + 0], Bh + 2 * jq);  // hi*hi
                        mma16816_u4(cc2, Aq[mh * 2 + 0], Bl + 2 * jq);  // hi*lo
                        mma16816_u4(cc2, Aq[mh * 2 + 1], Bh + 2 * jq);  // lo*hi
                    }
                }
            }
        };

        uint4 Acur[4], Anext[4];
        buildB(0, 0);
        loadA(Acur, gW, 0);
        __syncthreads();

        for (int c = 0; c < nch; ++c) {
            const int buf = c & 1;
            const uint32_t bbse = sbase + BBUF_OFF + buf * 8192;
            const int cn = (c + 1 < nch) ? c + 1 : c;

            loadA(Anext, gW + c, 1);          // ks=1 of this chunk (shadowed by ks0 compute)
            if (c + 1 < nch) buildB(c + 1, buf ^ 1);
            computeKs(Acur, bbse, 0);
            loadA(Acur, gW + cn, 0);          // ks=0 of next chunk (shadowed by ks1 compute)
            computeKs(Anext, bbse, 1);
            __syncthreads();                  // publish B buf^1
        }

        // ---- epilogue ----
        const float* bl = biasl[layer];
        const int fcbase = (layer == 2) ? 256 : layer * 128;
        const bool do_fc = (layer == 2) || (mt < 4);
        float bias4[4], fw4[4];
        #pragma unroll
        for (int rr = 0; rr < 4; ++rr) {
            const int row = mt * 32 + rr * 8 + r0;
            bias4[rr] = bl[row];
            fw4[rr] = do_fc ? fcW[fcbase + row] : 0.0f;
        }
        #pragma unroll
        for (int mh = 0; mh < 2; ++mh) {
            #pragma unroll
            for (int j = 0; j < 8; ++j) {
                #pragma unroll
                for (int e = 0; e < 4; ++e) {
                    const int rr = mh * 2 + (e >> 1);
                    const float v = fmaxf(acc[mh][j][e] + bias4[rr], 0.0f);
                    if (do_fc) {
                        fc_acc += fw4[rr] * v;
                    } else {
                        const int row = mt * 32 + mh * 16 + (e >> 1) * 8 + r0;
                        const int d   = 8 * j + 2 * (lane & 3) + (e & 1);
                        hs[(row - 128) * 65 + d] = v;
                    }
                }
            }
        }
        __syncthreads();
    }

    // final reduction (single batch)
    #pragma unroll
    for (int off = 16; off > 0; off >>= 1)
        fc_acc += __shfl_xor_sync(0xffffffffu, fc_acc, off);
    if (lane == 0) red[wid] = fc_acc;
    __syncthreads();
    if (tid == 0) {
        float s = 0.0f;
        #pragma unroll
        for (int w = 0; w < 8; ++w) s += red[w];
        out[B] = s + fcb[0];
    }
}

extern "C" void kernel_launch(void* const* d_in, const int* in_sizes, int n_in,
                              void* d_out, int out_size) {
    const float* x   = (const float*)d_in[0];
    const float* W0  = (const float*)d_in[1];
    const float* b0  = (const float*)d_in[2];
    const float* W1  = (const float*)d_in[3];
    const float* b1  = (const float*)d_in[4];
    const float* W2  = (const float*)d_in[5];
    const float* b2  = (const float*)d_in[6];
    const float* fcW = (const float*)d_in[7];
    const float* fcb = (const float*)d_in[8];
    float* out = (float*)d_out;

    cudaFuncSetAttribute(cin_mma_kernel, cudaFuncAttributeMaxDynamicSharedMemorySize, SMEM_BYTES);
    prep_kernel<<<NCHUNKS_TOT, 512>>>(W0, W1, W2);
    cin_mma_kernel<<<1024, THREADS, SMEM_BYTES>>>(x, b0, b1, b2, fcW, fcb, out);
}